// round 1
// baseline (speedup 1.0000x reference)
#include <cuda_runtime.h>
#include <math_constants.h>

#define B     4
#define CIN   3
#define NPTS  8192
#define COUT  64
#define KMAX  40
#define K0    10
#define K1    20
#define BN_EPS 1e-5f

// scratch: top-40 neighbor indices per (b, n), sorted by descending dist
__device__ int g_topk[B * NPTS * KMAX];

// ---------------------------------------------------------------------------
// Phase 1: brute-force top-40 nearest neighbors (largest negative sq dist).
// One thread per query point. Whole batch point cloud cached in smem as
// float4 (x, y, z, ||p||^2). Chunk-of-8 max pre-filter keeps the hot path
// branch-free; rare insertions go to a local-memory sorted list.
// ---------------------------------------------------------------------------
__global__ void __launch_bounds__(256, 1) topk_kernel(const float* __restrict__ x) {
    extern __shared__ float4 spts[];   // NPTS * 16B = 128 KB
    const int b = blockIdx.y;
    const int n = blockIdx.x * blockDim.x + threadIdx.x;
    const float* xb = x + (size_t)b * CIN * NPTS;

    for (int m = threadIdx.x; m < NPTS; m += blockDim.x) {
        float px = xb[m];
        float py = xb[NPTS + m];
        float pz = xb[2 * NPTS + m];
        float t = px * px;
        t = fmaf(py, py, t);
        t = fmaf(pz, pz, t);
        spts[m] = make_float4(px, py, pz, t);
    }
    __syncthreads();

    const float4 q = spts[n];
    const float qq = q.w;

    float bd[KMAX];
    int   bi[KMAX];
#pragma unroll
    for (int i = 0; i < KMAX; i++) { bd[i] = -CUDART_INF_F; bi[i] = 0; }
    float thr = -CUDART_INF_F;

    for (int m0 = 0; m0 < NPTS; m0 += 8) {
        float d[8];
        float cmax = -CUDART_INF_F;
#pragma unroll
        for (int u = 0; u < 8; u++) {
            float4 p = spts[m0 + u];
            float t = q.x * p.x;
            t = fmaf(q.y, p.y, t);
            t = fmaf(q.z, p.z, t);
            // d = 2*t - qq - ||p||^2 ; exactly 0.0 when p == q
            d[u] = fmaf(2.0f, t, -qq) - p.w;
            cmax = fmaxf(cmax, d[u]);
        }
        if (cmax > thr) {
#pragma unroll
            for (int u = 0; u < 8; u++) {
                if (d[u] > thr) {
                    int pos = KMAX - 1;
                    // strict compare: equal values keep earlier index first
                    while (pos > 0 && bd[pos - 1] < d[u]) {
                        bd[pos] = bd[pos - 1];
                        bi[pos] = bi[pos - 1];
                        pos--;
                    }
                    bd[pos] = d[u];
                    bi[pos] = m0 + u;
                    thr = bd[KMAX - 1];
                }
            }
        }
    }

    int* o = g_topk + ((size_t)b * NPTS + n) * KMAX;
#pragma unroll
    for (int i = 0; i < KMAX; i++) o[i] = bi[i];
}

// ---------------------------------------------------------------------------
// Phase 2: edge conv + BN (folded) + LeakyReLU (after max; monotone) + max.
// One block per (b, n), one thread per output channel o.
// y = Wd·nb + (Wc - Wd)·c ; fold BN: wd' = Wd*inv, base' = base*inv + bias.
// Scales are prefixes of the sorted top-40 list: j<10, j<20, j<40.
// ---------------------------------------------------------------------------
__global__ void __launch_bounds__(COUT) edgeconv_kernel(
    const float* __restrict__ x, const float* __restrict__ W,
    const float* __restrict__ gamma, const float* __restrict__ beta,
    const float* __restrict__ mean, const float* __restrict__ var,
    float* __restrict__ out)
{
    __shared__ float4 snb[KMAX];
    __shared__ float  scen[3];

    const int bn = blockIdx.x;
    const int b = bn / NPTS;
    const int n = bn % NPTS;
    const int tid = threadIdx.x;
    const float* xb = x + (size_t)b * CIN * NPTS;

    if (tid < KMAX) {
        int nb = g_topk[(size_t)bn * KMAX + tid];
        snb[tid] = make_float4(xb[nb], xb[NPTS + nb], xb[2 * NPTS + nb], 0.f);
    }
    if (tid < 3) scen[tid] = xb[tid * NPTS + n];
    __syncthreads();

    const float cx = scen[0], cy = scen[1], cz = scen[2];
    const int o = tid;

    float wd[3][3], basec[3];
#pragma unroll
    for (int s = 0; s < 3; s++) {
        const float* Ws = W + (s * COUT + o) * 6;
        float w0 = Ws[0], w1 = Ws[1], w2 = Ws[2];
        float w3 = Ws[3], w4 = Ws[4], w5 = Ws[5];
        int so = s * COUT + o;
        float inv  = gamma[so] * rsqrtf(var[so] + BN_EPS);
        float bias = beta[so] - mean[so] * inv;
        float base = (w3 - w0) * cx;
        base = fmaf(w4 - w1, cy, base);
        base = fmaf(w5 - w2, cz, base);
        wd[s][0] = w0 * inv; wd[s][1] = w1 * inv; wd[s][2] = w2 * inv;
        basec[s] = fmaf(base, inv, bias);
    }

    float m0 = -CUDART_INF_F, m1 = -CUDART_INF_F, m2 = -CUDART_INF_F;
#pragma unroll
    for (int j = 0; j < K0; j++) {
        float4 p = snb[j];
        float t0 = fmaf(wd[0][0], p.x, basec[0]);
        t0 = fmaf(wd[0][1], p.y, t0); t0 = fmaf(wd[0][2], p.z, t0);
        m0 = fmaxf(m0, t0);
        float t1 = fmaf(wd[1][0], p.x, basec[1]);
        t1 = fmaf(wd[1][1], p.y, t1); t1 = fmaf(wd[1][2], p.z, t1);
        m1 = fmaxf(m1, t1);
        float t2 = fmaf(wd[2][0], p.x, basec[2]);
        t2 = fmaf(wd[2][1], p.y, t2); t2 = fmaf(wd[2][2], p.z, t2);
        m2 = fmaxf(m2, t2);
    }
#pragma unroll
    for (int j = K0; j < K1; j++) {
        float4 p = snb[j];
        float t1 = fmaf(wd[1][0], p.x, basec[1]);
        t1 = fmaf(wd[1][1], p.y, t1); t1 = fmaf(wd[1][2], p.z, t1);
        m1 = fmaxf(m1, t1);
        float t2 = fmaf(wd[2][0], p.x, basec[2]);
        t2 = fmaf(wd[2][1], p.y, t2); t2 = fmaf(wd[2][2], p.z, t2);
        m2 = fmaxf(m2, t2);
    }
#pragma unroll
    for (int j = K1; j < KMAX; j++) {
        float4 p = snb[j];
        float t2 = fmaf(wd[2][0], p.x, basec[2]);
        t2 = fmaf(wd[2][1], p.y, t2); t2 = fmaf(wd[2][2], p.z, t2);
        m2 = fmaxf(m2, t2);
    }

    // LeakyReLU(0.2) applied once after max (monotone)
    m0 = fmaxf(m0, 0.2f * m0);
    m1 = fmaxf(m1, 0.2f * m1);
    m2 = fmaxf(m2, 0.2f * m2);

    // out[s][b][o][n]
    const size_t stride = (size_t)B * COUT * NPTS;
    size_t base = ((size_t)b * COUT + o) * NPTS + n;
    out[base]              = m0;
    out[base + stride]     = m1;
    out[base + 2 * stride] = m2;
}

extern "C" void kernel_launch(void* const* d_in, const int* in_sizes, int n_in,
                              void* d_out, int out_size) {
    const float* x     = (const float*)d_in[0];
    const float* W     = (const float*)d_in[1];
    const float* gamma = (const float*)d_in[2];
    const float* beta  = (const float*)d_in[3];
    const float* mean  = (const float*)d_in[4];
    const float* var   = (const float*)d_in[5];
    float* out = (float*)d_out;

    const int smem = NPTS * sizeof(float4);  // 128 KB
    cudaFuncSetAttribute(topk_kernel,
                         cudaFuncAttributeMaxDynamicSharedMemorySize, smem);

    dim3 g1(NPTS / 256, B);
    topk_kernel<<<g1, 256, smem>>>(x);
    edgeconv_kernel<<<B * NPTS, COUT>>>(x, W, gamma, beta, mean, var, out);
}

// round 2
// speedup vs baseline: 14.3911x; 14.3911x over previous
#include <cuda_runtime.h>
#include <math_constants.h>

#define B     4
#define CIN   3
#define NPTS  8192
#define COUT  64
#define KMAX  40
#define K0    10
#define K1    20
#define BN_EPS 1e-5f
#define FULL  0xFFFFFFFFu
#define TILE  2048
#define WPB   8          // warps (queries) per block

// packed points: (x, y, z, ||p||^2)
__device__ float4 g_pts[B * NPTS];
// top-40 neighbor indices per (b, n), sorted by descending dist
__device__ int g_topk[B * NPTS * KMAX];

// ---------------------------------------------------------------------------
// Phase 0: pack planar [B,3,N] into float4 (x,y,z,|p|^2)
// ---------------------------------------------------------------------------
__global__ void pack_kernel(const float* __restrict__ x) {
    int i = blockIdx.x * blockDim.x + threadIdx.x;   // 0 .. B*NPTS-1
    int b = i >> 13;
    int m = i & (NPTS - 1);
    const float* xb = x + (size_t)b * CIN * NPTS;
    float px = xb[m];
    float py = xb[NPTS + m];
    float pz = xb[2 * NPTS + m];
    float t = px * px;
    t = fmaf(py, py, t);
    t = fmaf(pz, pz, t);
    g_pts[i] = make_float4(px, py, pz, t);
}

// ---------------------------------------------------------------------------
// Phase 1: warp-per-query brute-force top-40.
// The sorted top-40 list lives distributed across the warp's registers:
//   slot s (0..31)  -> lane s,   d0/i0
//   slot s (32..63) -> lane s-32, d1/i1   (slots 40..63 are dead padding)
// Insert is a branch-free one-position shift via shuffles. Acceptance is
// warp-synchronized via ballot, so there is no divergence amplification.
// Candidates processed in ascending index order; strict compares reproduce
// lax.top_k stability (ties keep the lower index first).
// ---------------------------------------------------------------------------
__global__ void __launch_bounds__(32 * WPB) topk_kernel() {
    __shared__ float4 spts[TILE];   // 32 KB
    const int lane = threadIdx.x & 31;
    const int warp = threadIdx.x >> 5;
    const int qid  = blockIdx.x * WPB + warp;      // b*NPTS + n
    const int b    = qid >> 13;

    const float4 q = g_pts[qid];
    const float qq = q.w;
    const float qx = q.x, qy = q.y, qz = q.z;

    float d0 = -CUDART_INF_F, d1 = -CUDART_INF_F;
    int   i0 = 0, i1 = 0;
    float thr = -CUDART_INF_F;

    const float4* __restrict__ base = g_pts + b * NPTS;

    for (int tile = 0; tile < NPTS; tile += TILE) {
        __syncthreads();
        for (int i = threadIdx.x; i < TILE; i += 32 * WPB)
            spts[i] = base[tile + i];
        __syncthreads();

        for (int it = 0; it < TILE; it += 32) {
            float4 p = spts[it + lane];
            float t = qx * p.x;
            t = fmaf(qy, p.y, t);
            t = fmaf(qz, p.z, t);
            // d = 2*t - qq - ||p||^2 ; exactly 0.0 for the query itself
            float v = fmaf(2.0f, t, -qq) - p.w;

            unsigned mask = __ballot_sync(FULL, v > thr);
            while (mask) {
                int src = __ffs(mask) - 1;
                mask &= mask - 1;
                float vv = __shfl_sync(FULL, v, src);
                int   ii = tile + it + src;

                // shift flags: slot shifts right iff its value < vv (strict)
                bool s0 = d0 < vv;
                bool s1 = d1 < vv;
                float d0u = __shfl_up_sync(FULL, d0, 1);
                int   i0u = __shfl_up_sync(FULL, i0, 1);
                float d1u = __shfl_up_sync(FULL, d1, 1);
                int   i1u = __shfl_up_sync(FULL, i1, 1);
                float d31 = __shfl_sync(FULL, d0, 31);
                int   i31 = __shfl_sync(FULL, i0, 31);
                if (lane == 0) { d1u = d31; i1u = i31; }
                // predecessor shift flag: if pred also shifts, take its value;
                // otherwise this slot is the insert position.
                bool p0 = (lane > 0) && (d0u < vv);
                bool p1 = (d1u < vv);
                if (s0) { d0 = p0 ? d0u : vv; i0 = p0 ? i0u : ii; }
                if (s1) { d1 = p1 ? d1u : vv; i1 = p1 ? i1u : ii; }
                // new 40th value = slot 39 = row1 lane 7
                thr = __shfl_sync(FULL, d1, 7);
            }
        }
    }

    int* o = g_topk + (size_t)qid * KMAX;
    o[lane] = i0;
    if (lane < 8) o[32 + lane] = i1;
}

// ---------------------------------------------------------------------------
// Phase 2: edge conv + folded BN + LeakyReLU (after max; monotone) + max.
// One block per (b, n), one thread per output channel o.
// Scales are prefixes of the sorted top-40 list: j<10, j<20, j<40.
// ---------------------------------------------------------------------------
__global__ void __launch_bounds__(COUT) edgeconv_kernel(
    const float* __restrict__ x, const float* __restrict__ W,
    const float* __restrict__ gamma, const float* __restrict__ beta,
    const float* __restrict__ mean, const float* __restrict__ var,
    float* __restrict__ out)
{
    __shared__ float4 snb[KMAX];
    __shared__ float  scen[3];

    const int bn = blockIdx.x;
    const int b = bn >> 13;
    const int n = bn & (NPTS - 1);
    const int tid = threadIdx.x;
    const float* xb = x + (size_t)b * CIN * NPTS;

    if (tid < KMAX) {
        int nb = g_topk[(size_t)bn * KMAX + tid];
        snb[tid] = make_float4(xb[nb], xb[NPTS + nb], xb[2 * NPTS + nb], 0.f);
    }
    if (tid < 3) scen[tid] = xb[tid * NPTS + n];
    __syncthreads();

    const float cx = scen[0], cy = scen[1], cz = scen[2];
    const int o = tid;

    float wd[3][3], basec[3];
#pragma unroll
    for (int s = 0; s < 3; s++) {
        const float* Ws = W + (s * COUT + o) * 6;
        float w0 = Ws[0], w1 = Ws[1], w2 = Ws[2];
        float w3 = Ws[3], w4 = Ws[4], w5 = Ws[5];
        int so = s * COUT + o;
        float inv  = gamma[so] * rsqrtf(var[so] + BN_EPS);
        float bias = beta[so] - mean[so] * inv;
        float base = (w3 - w0) * cx;
        base = fmaf(w4 - w1, cy, base);
        base = fmaf(w5 - w2, cz, base);
        wd[s][0] = w0 * inv; wd[s][1] = w1 * inv; wd[s][2] = w2 * inv;
        basec[s] = fmaf(base, inv, bias);
    }

    float m0 = -CUDART_INF_F, m1 = -CUDART_INF_F, m2 = -CUDART_INF_F;
#pragma unroll
    for (int j = 0; j < K0; j++) {
        float4 p = snb[j];
        float t0 = fmaf(wd[0][0], p.x, basec[0]);
        t0 = fmaf(wd[0][1], p.y, t0); t0 = fmaf(wd[0][2], p.z, t0);
        m0 = fmaxf(m0, t0);
        float t1 = fmaf(wd[1][0], p.x, basec[1]);
        t1 = fmaf(wd[1][1], p.y, t1); t1 = fmaf(wd[1][2], p.z, t1);
        m1 = fmaxf(m1, t1);
        float t2 = fmaf(wd[2][0], p.x, basec[2]);
        t2 = fmaf(wd[2][1], p.y, t2); t2 = fmaf(wd[2][2], p.z, t2);
        m2 = fmaxf(m2, t2);
    }
#pragma unroll
    for (int j = K0; j < K1; j++) {
        float4 p = snb[j];
        float t1 = fmaf(wd[1][0], p.x, basec[1]);
        t1 = fmaf(wd[1][1], p.y, t1); t1 = fmaf(wd[1][2], p.z, t1);
        m1 = fmaxf(m1, t1);
        float t2 = fmaf(wd[2][0], p.x, basec[2]);
        t2 = fmaf(wd[2][1], p.y, t2); t2 = fmaf(wd[2][2], p.z, t2);
        m2 = fmaxf(m2, t2);
    }
#pragma unroll
    for (int j = K1; j < KMAX; j++) {
        float4 p = snb[j];
        float t2 = fmaf(wd[2][0], p.x, basec[2]);
        t2 = fmaf(wd[2][1], p.y, t2); t2 = fmaf(wd[2][2], p.z, t2);
        m2 = fmaxf(m2, t2);
    }

    m0 = fmaxf(m0, 0.2f * m0);
    m1 = fmaxf(m1, 0.2f * m1);
    m2 = fmaxf(m2, 0.2f * m2);

    const size_t stride = (size_t)B * COUT * NPTS;
    size_t baseo = ((size_t)b * COUT + o) * NPTS + n;
    out[baseo]              = m0;
    out[baseo + stride]     = m1;
    out[baseo + 2 * stride] = m2;
}

extern "C" void kernel_launch(void* const* d_in, const int* in_sizes, int n_in,
                              void* d_out, int out_size) {
    const float* x     = (const float*)d_in[0];
    const float* W     = (const float*)d_in[1];
    const float* gamma = (const float*)d_in[2];
    const float* beta  = (const float*)d_in[3];
    const float* mean  = (const float*)d_in[4];
    const float* var   = (const float*)d_in[5];
    float* out = (float*)d_out;

    pack_kernel<<<(B * NPTS) / 256, 256>>>(x);
    topk_kernel<<<(B * NPTS) / WPB, 32 * WPB>>>();
    edgeconv_kernel<<<B * NPTS, COUT>>>(x, W, gamma, beta, mean, var, out);
}